// round 15
// baseline (speedup 1.0000x reference)
#include <cuda_runtime.h>
#include <cuda_bf16.h>
#include <cstdint>

// ----------------------------------------------------------------------------
// DCRNN decoder cell (2 layers), N=2048, B=32, UNITS=64, 5 Chebyshev terms.
// Diffusion + W-GEMMs on mma.sync bf16 (sm_80 baseline ISA; tcgen05 is gated
// off by the harness's .target sm_103 lowering).
// Chain (reference quirk — x0 mutates between supports):
//   buf1 = S0@buf0 ; buf2 = 2*S0@buf1 - buf0 ; buf3 = S1@buf1 ; buf4 = 2*S1@buf3 - buf1
// Diffusion tile: 128x128, 256 threads, k-chunk 64, 3-stage cp.async, occ 2.
// Disjoint per-layer buffers:
//   fp32 g_X:  L0 buf0=0, buf1=1 (stride 2080) | L1 buf0=2, buf1=3 (stride 4096)
//   bf16 g_Xh: L0 terms 0..4 (stride 2112)     | L1 terms 5..9 (stride 4096)
// All device-symbol addressing happens INSIDE kernels (integer indices only).
// ----------------------------------------------------------------------------

#define NN   2048
#define BB   32
#define UU   64
static const size_t BUFSZ = 2048ull * 4096ull;
static const size_t MIRSZ = 2048ull * 4096ull;

__device__ __nv_bfloat16 g_S0h[2048ull * 2048ull];
__device__ __nv_bfloat16 g_S1h[2048ull * 2048ull];
__device__ float g_inv_row[NN];
__device__ float g_inv_col[NN];
__device__ float g_X[4ull * 2048ull * 4096ull];           // fp32 bufs
__device__ __nv_bfloat16 g_Xh[10ull * 2048ull * 4096ull]; // bf16 mirrors
__device__ float g_U[2048ull * 32ull * 64ull];            // u gate, [n][b][o]
__device__ __nv_bfloat16 g_Wr[199680];                    // 4 reordered weight sets

#define WR_G0 0
#define WR_C0 51200
#define WR_G1 76800
#define WR_C1 158720

// ----------------------------- PTX helpers ----------------------------------

__device__ __forceinline__ uint32_t smem_u32(const void* p) {
    uint32_t r;
    asm("{ .reg .u64 t; cvta.to.shared.u64 t, %1; cvt.u32.u64 %0, t; }" : "=r"(r) : "l"(p));
    return r;
}

__device__ __forceinline__ void cp16(uint32_t sm, const void* g, int srcsize) {
    asm volatile("cp.async.cg.shared.global [%0], [%1], 16, %2;"
                 :: "r"(sm), "l"(g), "r"(srcsize) : "memory");
}
#define CP_COMMIT() asm volatile("cp.async.commit_group;" ::: "memory")
#define CP_WAIT1()  asm volatile("cp.async.wait_group 1;" ::: "memory")
#define CP_WAIT2()  asm volatile("cp.async.wait_group 2;" ::: "memory")

__device__ __forceinline__ void ldmA(uint32_t* r, uint32_t addr) {
    asm volatile("ldmatrix.sync.aligned.m8n8.x4.shared.b16 {%0,%1,%2,%3}, [%4];"
                 : "=r"(r[0]), "=r"(r[1]), "=r"(r[2]), "=r"(r[3]) : "r"(addr));
}

__device__ __forceinline__ void ldm4t(uint32_t* r, uint32_t addr) {
    asm volatile("ldmatrix.sync.aligned.m8n8.x4.trans.shared.b16 {%0,%1,%2,%3}, [%4];"
                 : "=r"(r[0]), "=r"(r[1]), "=r"(r[2]), "=r"(r[3]) : "r"(addr));
}

__device__ __forceinline__ void mma16816(float* c, const uint32_t* a, const uint32_t* b) {
    asm volatile(
        "mma.sync.aligned.m16n8k16.row.col.f32.bf16.bf16.f32 "
        "{%0,%1,%2,%3},{%4,%5,%6,%7},{%8,%9},{%0,%1,%2,%3};"
        : "+f"(c[0]), "+f"(c[1]), "+f"(c[2]), "+f"(c[3])
        : "r"(a[0]), "r"(a[1]), "r"(a[2]), "r"(a[3]), "r"(b[0]), "r"(b[1]));
}

// ------------------------------ support prep --------------------------------

__global__ void rowsum_kernel(const float* __restrict__ adj) {
    int row = blockIdx.x, tid = threadIdx.x;
    float s = 0.f;
    for (int k = tid; k < NN; k += 256) s += adj[(size_t)row * NN + k];
    __shared__ float sm[256];
    sm[tid] = s; __syncthreads();
    for (int o = 128; o > 0; o >>= 1) { if (tid < o) sm[tid] += sm[tid + o]; __syncthreads(); }
    if (tid == 0) g_inv_row[row] = 1.0f / fmaxf(sm[0], 1e-8f);
}

__global__ void colsum_kernel(const float* __restrict__ adj) {
    int j = blockIdx.x * 32 + threadIdx.x;
    int ty = threadIdx.y;
    float s = 0.f;
    for (int k = ty; k < NN; k += 8) s += adj[(size_t)k * NN + j];
    __shared__ float sm[8][32];
    sm[ty][threadIdx.x] = s; __syncthreads();
    if (ty == 0) {
        float t = 0.f;
        #pragma unroll
        for (int r = 0; r < 8; r++) t += sm[r][threadIdx.x];
        g_inv_col[j] = 1.0f / fmaxf(t, 1e-8f);
    }
}

__global__ void build_supports(const float* __restrict__ adj) {
    __shared__ float t[32][33];
    int tx = threadIdx.x, ty = threadIdx.y;
    int j0 = blockIdx.x * 32, i0 = blockIdx.y * 32;
    #pragma unroll
    for (int s = 0; s < 4; s++) {
        int r = ty + s * 8;
        t[r][tx] = adj[(size_t)(i0 + r) * NN + j0 + tx];
    }
    __syncthreads();
    float icol = g_inv_col[j0 + tx];
    float irow = g_inv_row[i0 + tx];
    #pragma unroll
    for (int s = 0; s < 4; s++) {
        int r = ty + s * 8;
        g_S1h[(size_t)(i0 + r) * NN + j0 + tx] = __float2bfloat16(t[r][tx] * icol);
        g_S0h[(size_t)(j0 + r) * NN + i0 + tx] = __float2bfloat16(t[tx][r] * irow);
    }
}

// ----------------- x0 packing (both layers, one launch) ----------------------

__global__ void pack_kernel(const float* __restrict__ inp,
                            const float* __restrict__ hx0,
                            const float* __restrict__ hx1)
{
    __shared__ float sm[65 * 33];
    int n = blockIdx.x, tid = threadIdx.x;
    if (blockIdx.y == 0) {
        for (int idx = tid; idx < 2048; idx += 256) {
            int b = idx >> 6, u = idx & 63;
            sm[(u + 1) * 33 + b] = hx0[(size_t)b * (NN * UU) + (size_t)n * UU + u];
        }
        if (tid < 32) sm[tid] = inp[(size_t)tid * NN + n];
        __syncthreads();
        for (int idx = tid; idx < 65 * 32; idx += 256) {
            int f = idx >> 5, b = idx & 31;
            float v = sm[f * 33 + b];
            g_X[(size_t)n * 2080 + idx] = v;
            g_Xh[(size_t)n * 2112 + idx] = __float2bfloat16(v);
        }
    } else {
        for (int idx = tid; idx < 2048; idx += 256) {
            int b = idx >> 6, u = idx & 63;
            sm[u * 33 + b] = hx1[(size_t)b * (NN * UU) + (size_t)n * UU + u];
        }
        __syncthreads();
        for (int idx = tid; idx < 64 * 32; idx += 256) {
            int f = idx >> 5, b = idx & 31;
            float v = sm[f * 33 + b];
            g_X[2 * BUFSZ + (size_t)n * 4096 + (size_t)(64 + f) * 32 + b] = v;
            g_Xh[5 * MIRSZ + (size_t)n * 4096 + (size_t)(64 + f) * 32 + b] = __float2bfloat16(v);
        }
    }
}

// ------------------- diffusion GEMM (mma.sync bf16) -------------------------
// CTA 128x128, k-chunk 64, 3-stage cp.async; 256 threads = 8 warps (2M x 4N);
// occupancy 2. Halved barrier/wait count vs k-chunk 32.

#define D_AST 72              // A smem row stride (bf16): 64 data + 8 pad (144B)
#define D_BST 136             // B smem row stride (bf16): 272B
#define D_ASB (128 * D_AST * 2)   // 18432 B per A stage
#define D_BSB (64 * D_BST * 2)    // 17408 B per B stage
#define DIFF_SMEM (3 * (D_ASB + D_BSB))   // 107520 bytes

__device__ __forceinline__ void diff_body(
    const __nv_bfloat16* __restrict__ S, const __nv_bfloat16* __restrict__ Xh,
    float* __restrict__ Y, const float* __restrict__ Xp, __nv_bfloat16* __restrict__ Yh,
    int ld, int ldh, int colOff, int colEnd,
    float alpha, float beta, uint32_t aBase, uint32_t bBase)
{
    const int tid  = threadIdx.x;
    const int row0 = blockIdx.y * 128;
    const int col0 = colOff + blockIdx.x * 128;

    const int wid = tid >> 5, lane = tid & 31;
    const int wm = (wid & 1) * 64;
    const int wn = (wid >> 1) * 32;

    const int aR = (lane & 7) + ((lane >> 3) & 1) * 8;
    const int aC = (lane >> 4) * 8;
    const int bR = ((lane >> 3) & 1) * 8 + (lane & 7);
    const int bC = (lane >> 4) * 8;

    float acc[4][4][4];
    #pragma unroll
    for (int mi = 0; mi < 4; mi++)
        #pragma unroll
        for (int ni = 0; ni < 4; ni++)
            #pragma unroll
            for (int q = 0; q < 4; q++) acc[mi][ni][q] = 0.f;

    // stage s = i % 3; A: 128 rows x 8 uint4 (64 k), B: 64 rows x 16 uint4
    auto LOAD = [&](int i) {
        const int k0 = i * 64, s = i % 3;
        #pragma unroll
        for (int t = 0; t < 4; t++) {           // 1024 uint4 for A
            int aIdx = t * 256 + tid;
            int r = aIdx >> 3, kq = aIdx & 7;
            cp16(aBase + s * D_ASB + (uint32_t)(r * D_AST + kq * 8) * 2,
                 S + (size_t)(row0 + r) * NN + k0 + kq * 8, 16);
        }
        #pragma unroll
        for (int t = 0; t < 4; t++) {           // 1024 uint4 for B
            int bIdx = t * 256 + tid;
            int kr = bIdx >> 4, nq = bIdx & 15;
            int c = col0 + nq * 8;
            cp16(bBase + s * D_BSB + (uint32_t)(kr * D_BST + nq * 8) * 2,
                 Xh + (size_t)(k0 + kr) * ldh + c, (c < colEnd) ? 16 : 0);
        }
    };

    LOAD(0); CP_COMMIT();
    LOAD(1); CP_COMMIT();

    for (int i = 0; i < 32; i++) {
        CP_WAIT1();
        __syncthreads();                // iter i-1 reads done before stage overwrite
        if (i + 2 < 32) LOAD(i + 2);
        CP_COMMIT();

        const int s = i % 3;
        #pragma unroll
        for (int kc = 0; kc < 64; kc += 16) {
            uint32_t af[4][4], bf[2][4];
            #pragma unroll
            for (int mi = 0; mi < 4; mi++)
                ldmA(af[mi], aBase + s * D_ASB +
                     (uint32_t)((wm + mi * 16 + aR) * D_AST + kc + aC) * 2);
            #pragma unroll
            for (int np = 0; np < 2; np++)
                ldm4t(bf[np], bBase + s * D_BSB +
                      (uint32_t)((kc + bR) * D_BST + wn + np * 16 + bC) * 2);
            #pragma unroll
            for (int mi = 0; mi < 4; mi++)
                #pragma unroll
                for (int ni = 0; ni < 4; ni++)
                    mma16816(acc[mi][ni], af[mi], &bf[ni >> 1][(ni & 1) * 2]);
        }
    }

    const int g = lane >> 2, t2 = (lane & 3) * 2;
    #pragma unroll
    for (int mi = 0; mi < 4; mi++) {
        #pragma unroll
        for (int half = 0; half < 2; half++) {
            int r = row0 + wm + mi * 16 + g + half * 8;
            float* yRow = Y ? (Y + (size_t)r * ld) : nullptr;
            const float* pRow = Xp ? (Xp + (size_t)r * ld) : nullptr;
            __nv_bfloat16* hRow = Yh + (size_t)r * ldh;
            #pragma unroll
            for (int ni = 0; ni < 4; ni++) {
                int c = col0 + wn + ni * 8 + t2;
                if (c < colEnd) {
                    float vx = alpha * acc[mi][ni][half * 2 + 0];
                    float vy = alpha * acc[mi][ni][half * 2 + 1];
                    if (pRow) {
                        float2 p = *(const float2*)(pRow + c);
                        vx = fmaf(beta, p.x, vx);
                        vy = fmaf(beta, p.y, vy);
                    }
                    if (yRow) *(float2*)(yRow + c) = make_float2(vx, vy);
                    *(__nv_bfloat162*)(hRow + c) = __floats2bfloat162_rn(vx, vy);
                }
            }
        }
    }
}

__global__ void __launch_bounds__(256, 2)
diff_mma(int sSel, int xhIdx, int yIdx, int prevIdx, int yhIdx,
         int ld, int ldh, int colOff, int colEnd, float alpha, float beta)
{
    extern __shared__ __nv_bfloat16 dsm[];
    const uint32_t aBase = smem_u32(dsm);
    diff_body(sSel ? g_S1h : g_S0h,
              g_Xh + (size_t)xhIdx * MIRSZ,
              (yIdx >= 0) ? (g_X + (size_t)yIdx * BUFSZ) : nullptr,
              (prevIdx >= 0) ? (g_X + (size_t)prevIdx * BUFSZ) : nullptr,
              g_Xh + (size_t)yhIdx * MIRSZ,
              ld, ldh, colOff, colEnd, alpha, beta, aBase, aBase + 3 * D_ASB);
}

// buf2 and buf3 both depend only on buf1 -> one launch; layer selects buffers.
__global__ void __launch_bounds__(256, 2)
diff_pair(int layer, int ld, int ldh, int colOff, int colEnd)
{
    extern __shared__ __nv_bfloat16 dsm[];
    const uint32_t aBase = smem_u32(dsm);
    const int mb = layer * 5, fb = layer * 2;
    if (blockIdx.z == 0) {
        diff_body(g_S0h, g_Xh + (size_t)(mb + 1) * MIRSZ, nullptr,
                  g_X + (size_t)(fb + 0) * BUFSZ, g_Xh + (size_t)(mb + 2) * MIRSZ,
                  ld, ldh, colOff, colEnd, 2.0f, -1.0f, aBase, aBase + 3 * D_ASB);
    } else {
        diff_body(g_S1h, g_Xh + (size_t)(mb + 1) * MIRSZ, nullptr,
                  nullptr, g_Xh + (size_t)(mb + 3) * MIRSZ,
                  ld, ldh, colOff, colEnd, 1.0f, 0.0f, aBase, aBase + 3 * D_ASB);
    }
}

// --------------- weight reorder (all four sets, one launch) ------------------

__device__ __forceinline__ void wprep_one(const float* __restrict__ W,
                                          __nv_bfloat16* __restrict__ dst,
                                          int F, int Fp, int O) {
    int idx = blockIdx.x * 256 + threadIdx.x;
    if (idx >= 5 * Fp * O) return;
    int o = idx % O;
    int rest = idx / O;
    int f = rest % Fp;
    int m = rest / Fp;
    dst[idx] = (f < F) ? __float2bfloat16(W[(size_t)(f * 5 + m) * O + o])
                       : __float2bfloat16(0.f);
}

__global__ void wprep_all(const float* wg0, const float* wc0,
                          const float* wg1, const float* wc1) {
    switch (blockIdx.y) {
        case 0: wprep_one(wg0, g_Wr + WR_G0, 65, 80, 128); break;
        case 1: wprep_one(wc0, g_Wr + WR_C0, 65, 80, 64); break;
        case 2: wprep_one(wg1, g_Wr + WR_G1, 128, 128, 128); break;
        case 3: wprep_one(wc1, g_Wr + WR_C1, 128, 128, 64); break;
    }
}

// ------------------------ W-GEMM (mma.sync bf16) ----------------------------

#define W_ST 136

template <int O, int MODE>
__global__ void __launch_bounds__(256)
wgemm_mma(int F, int Fp, int ld, int ldh, int xhBase, int wrOff,
          const float* __restrict__ bias,
          const float* __restrict__ hx, float* __restrict__ hout,
          int FinB, int gFpBuf, int gMirBuf, int packFlag)
{
    constexpr int NI = O / 32;
    __shared__ __nv_bfloat16 As[4][16 * W_ST];
    __shared__ __nv_bfloat16 Ws[4][16 * W_ST];

    const __nv_bfloat16* __restrict__ XhL = g_Xh + (size_t)xhBase * MIRSZ;
    const __nv_bfloat16* __restrict__ Wr  = g_Wr + wrOff;

    const int tid = threadIdx.x;
    const int n0  = blockIdx.x * 4;
    const int wid = tid >> 5, lane = tid & 31;
    const int wm  = (wid & 1) * 64;
    const int wn  = (wid >> 1) * (O / 4);

    const int chunksPerM = Fp / 16;
    const int total = 5 * chunksPerM;

    const int kfA = tid >> 4, lnA = (tid >> 2) & 3, qA = tid & 3;
    const int kfW = tid >> 4, qW = tid & 15;

    const int ktA = (lane & 7) + ((lane >> 4) & 1) * 8;
    const int mcA = ((lane >> 3) & 1) * 8;
    const int bR = ((lane >> 3) & 1) * 8 + (lane & 7);
    const int bC = (lane >> 4) * 8;

    const uint32_t asB = smem_u32(As), wsB = smem_u32(Ws);

    float acc[4][NI][4];
    #pragma unroll
    for (int mt = 0; mt < 4; mt++)
        #pragma unroll
        for (int ni = 0; ni < NI; ni++)
            #pragma unroll
            for (int q = 0; q < 4; q++) acc[mt][ni][q] = 0.f;

    auto LOAD = [&](int ic) {
        const int s = ic & 3;
        const int mi = ic / chunksPerM;
        const int fc = (ic % chunksPerM) * 16;
        const int f = fc + kfA;
        cp16(asB + (uint32_t)(s * 16 * W_ST + kfA * W_ST + lnA * 32 + qA * 8) * 2,
             XhL + (size_t)mi * MIRSZ + (size_t)(n0 + lnA) * ldh + (size_t)f * 32 + qA * 8,
             (f < F) ? 16 : 0);
        if (qW * 8 < O)
            cp16(wsB + (uint32_t)(s * 16 * W_ST + kfW * W_ST + qW * 8) * 2,
                 Wr + ((size_t)mi * Fp + fc + kfW) * O + qW * 8, 16);
    };

    LOAD(0); CP_COMMIT();
    LOAD(1); CP_COMMIT();
    LOAD(2); CP_COMMIT();

    for (int ic = 0; ic < total; ic++) {
        CP_WAIT2();
        __syncthreads();
        if (ic + 3 < total) LOAD(ic + 3);
        CP_COMMIT();

        const int s = ic & 3;
        uint32_t af[4][4];
        #pragma unroll
        for (int mt = 0; mt < 4; mt++)
            ldm4t(af[mt], asB +
                  (uint32_t)(s * 16 * W_ST + ktA * W_ST + wm + mt * 16 + mcA) * 2);
        uint32_t bf[(NI + 1) / 2][4];
        #pragma unroll
        for (int np = 0; np < (NI + 1) / 2; np++)
            ldm4t(bf[np], wsB +
                  (uint32_t)(s * 16 * W_ST + bR * W_ST + wn + np * 16 + bC) * 2);
        #pragma unroll
        for (int mt = 0; mt < 4; mt++)
            #pragma unroll
            for (int ni = 0; ni < NI; ni++)
                mma16816(acc[mt][ni], af[mt], &bf[ni >> 1][(ni & 1) * 2]);
    }

    const int g = lane >> 2, t2 = (lane & 3) * 2;
    #pragma unroll
    for (int mt = 0; mt < 4; mt++) {
        #pragma unroll
        for (int half = 0; half < 2; half++) {
            int r = wm + mt * 16 + g + half * 8;
            int ln = r >> 5, b = r & 31, n = n0 + ln;
            #pragma unroll
            for (int ni = 0; ni < NI; ni++) {
                int o = wn + ni * 8 + t2;
                float p0 = acc[mt][ni][half * 2 + 0] + bias[o];
                float p1 = acc[mt][ni][half * 2 + 1] + bias[o + 1];
                if (MODE == 0) {
                    float v0 = 1.0f / (1.0f + __expf(-p0));
                    float v1 = 1.0f / (1.0f + __expf(-p1));
                    if (o < 64) {
                        float hp0 = hx[(size_t)b * (NN * UU) + (size_t)n * UU + o];
                        float hp1 = hx[(size_t)b * (NN * UU) + (size_t)n * UU + o + 1];
                        float r0 = v0 * hp0, r1 = v1 * hp1;
                        float* dF = g_X + (size_t)gFpBuf * BUFSZ + (size_t)n * ld + FinB;
                        __nv_bfloat16* dH = g_Xh + (size_t)gMirBuf * MIRSZ + (size_t)n * ldh + FinB;
                        dF[(size_t)o * 32 + b] = r0;
                        dF[(size_t)(o + 1) * 32 + b] = r1;
                        dH[(size_t)o * 32 + b] = __float2bfloat16(r0);
                        dH[(size_t)(o + 1) * 32 + b] = __float2bfloat16(r1);
                    } else {
                        *(float2*)&g_U[((size_t)n * 32 + b) * 64 + (o - 64)] = make_float2(v0, v1);
                    }
                } else {
                    float c0 = tanhf(p0), c1 = tanhf(p1);
                    float2 uv = *(const float2*)&g_U[((size_t)n * 32 + b) * 64 + o];
                    float hp0 = hx[(size_t)b * (NN * UU) + (size_t)n * UU + o];
                    float hp1 = hx[(size_t)b * (NN * UU) + (size_t)n * UU + o + 1];
                    float h0v = uv.x * hp0 + (1.0f - uv.x) * c0;
                    float h1v = uv.y * hp1 + (1.0f - uv.y) * c1;
                    *(float2*)&hout[(size_t)b * (NN * UU) + (size_t)n * UU + o] = make_float2(h0v, h1v);
                    if (packFlag) {  // write h0 straight into L1 buf0 (bufs 2 / 5)
                        float* pF = g_X + 2 * BUFSZ + (size_t)n * 4096;
                        __nv_bfloat16* pH = g_Xh + 5 * MIRSZ + (size_t)n * 4096;
                        pF[(size_t)o * 32 + b] = h0v;
                        pF[(size_t)(o + 1) * 32 + b] = h1v;
                        pH[(size_t)o * 32 + b] = __float2bfloat16(h0v);
                        pH[(size_t)(o + 1) * 32 + b] = __float2bfloat16(h1v);
                    }
                }
            }
        }
    }
}

// ------------------------------ projection ----------------------------------

__global__ void proj_kernel(const float* __restrict__ h1, const float* __restrict__ wp,
                            const float* __restrict__ bp, float* __restrict__ out)
{
    int warp = (blockIdx.x * blockDim.x + threadIdx.x) >> 5;
    int lane = threadIdx.x & 31;
    if (warp >= BB * NN) return;
    int b = warp >> 11, n = warp & (NN - 1);
    const float* hr = h1 + (size_t)b * (NN * UU) + (size_t)n * UU;
    float s = hr[lane] * wp[lane] + hr[lane + 32] * wp[lane + 32];
    #pragma unroll
    for (int o = 16; o > 0; o >>= 1) s += __shfl_down_sync(0xffffffffu, s, o);
    if (lane == 0) out[(size_t)b * NN + n] = s + bp[0];
}

// ------------------------------ driver --------------------------------------

static void run_diffusion(int layer, int colOff, int colW, int ld, int ldh) {
    int tiles = (colW + 127) / 128;
    int ce = colOff + colW;
    int mb = layer * 5, fb = layer * 2;
    diff_mma <<<dim3(tiles, 16),    256, DIFF_SMEM>>>(0, mb + 0, fb + 1, -1, mb + 1,
                                                      ld, ldh, colOff, ce, 1.0f, 0.0f);
    diff_pair<<<dim3(tiles, 16, 2), 256, DIFF_SMEM>>>(layer, ld, ldh, colOff, ce);
    diff_mma <<<dim3(tiles, 16),    256, DIFF_SMEM>>>(1, mb + 3, -1, fb + 1, mb + 4,
                                                      ld, ldh, colOff, ce, 2.0f, -1.0f);
}

extern "C" void kernel_launch(void* const* d_in, const int* in_sizes, int n_in,
                              void* d_out, int out_size)
{
    const float* inputs = (const float*)d_in[0];
    const float* hidden = (const float*)d_in[1];
    const float* adj    = (const float*)d_in[2];
    const float* wg0    = (const float*)d_in[3];
    const float* bg0    = (const float*)d_in[4];
    const float* wc0    = (const float*)d_in[5];
    const float* bc0    = (const float*)d_in[6];
    const float* wg1    = (const float*)d_in[7];
    const float* bg1    = (const float*)d_in[8];
    const float* wc1    = (const float*)d_in[9];
    const float* bc1    = (const float*)d_in[10];
    const float* wproj  = (const float*)d_in[11];
    const float* bproj  = (const float*)d_in[12];

    float* out = (float*)d_out;                       // (B, N)
    float* h0  = out + (size_t)BB * NN;               // (B, N*U)
    float* h1  = h0 + (size_t)BB * NN * UU;           // (B, N*U)
    const float* hx0 = hidden;
    const float* hx1 = hidden + (size_t)BB * NN * UU;

    cudaFuncSetAttribute(diff_mma,  cudaFuncAttributeMaxDynamicSharedMemorySize, DIFF_SMEM);
    cudaFuncSetAttribute(diff_pair, cudaFuncAttributeMaxDynamicSharedMemorySize, DIFF_SMEM);

    // startup: supports + input packing + all weight reorders
    rowsum_kernel<<<NN, 256>>>(adj);
    colsum_kernel<<<NN / 32, dim3(32, 8)>>>(adj);
    build_supports<<<dim3(NN / 32, NN / 32), dim3(32, 8)>>>(adj);
    pack_kernel<<<dim3(NN, 2), 256>>>(inputs, hx0, hx1);
    wprep_all<<<dim3(320, 4), 256>>>(wg0, wc0, wg1, wc1);

    // ---- layer 0 (F = 65 -> Fp = 80; fp32 ld = 2080, bf16 ldh = 2112) ----
    run_diffusion(0, 0, 2080, 2080, 2112);
    wgemm_mma<128, 0><<<NN / 4, 256>>>(65, 80, 2080, 2112, 0, WR_G0, bg0, hx0,
                                       nullptr, 32, 0, 0, 0);
    run_diffusion(0, 32, 2048, 2080, 2112);
    wgemm_mma<64, 1><<<NN / 4, 256>>>(65, 80, 2080, 2112, 0, WR_C0, bc0, hx0,
                                      h0, 0, 0, 0, 1);

    // ---- layer 1 (F = 128 = Fp; ld = ldh = 4096; bufs fp32 2/3, mirrors 5..9) ----
    run_diffusion(1, 0, 4096, 4096, 4096);
    wgemm_mma<128, 0><<<NN / 4, 256>>>(128, 128, 4096, 4096, 5, WR_G1, bg1, hx1,
                                       nullptr, 2048, 2, 5, 0);
    run_diffusion(1, 2048, 2048, 4096, 4096);
    wgemm_mma<64, 1><<<NN / 4, 256>>>(128, 128, 4096, 4096, 5, WR_C1, bc1, hx1,
                                      h1, 0, 0, 0, 0);

    // projection
    proj_kernel<<<(BB * NN) / 8, 256>>>(h1, wproj, bproj, out);
}

// round 16
// speedup vs baseline: 1.0700x; 1.0700x over previous
#include <cuda_runtime.h>
#include <cuda_bf16.h>
#include <cstdint>

// ----------------------------------------------------------------------------
// DCRNN decoder cell (2 layers), N=2048, B=32, UNITS=64, 5 Chebyshev terms.
// Diffusion + W-GEMMs on mma.sync bf16 (sm_80 baseline ISA; tcgen05 is gated
// off by the harness's .target sm_103 lowering).
// Chain (reference quirk — x0 mutates between supports):
//   buf1 = S0@buf0 ; buf2 = 2*S0@buf1 - buf0 ; buf3 = S1@buf1 ; buf4 = 2*S1@buf3 - buf1
// ALL term storage is bf16 (fp32 term buffers removed — 'prev' operands read
// the bf16 mirrors; rounding is same order as existing bf16 GEMM inputs).
// Diffusion tile: 128x128, 256 threads, k-chunk 32, 4-stage cp.async, occ 2
// (measured-best geometry: R11/R14).
// Mirrors g_Xh: L0 terms 0..4 (stride 2112) | L1 terms 5..9 (stride 4096).
// All device-symbol addressing happens INSIDE kernels (integer indices only).
// ----------------------------------------------------------------------------

#define NN   2048
#define BB   32
#define UU   64
static const size_t MIRSZ = 2048ull * 4096ull;

__device__ __nv_bfloat16 g_S0h[2048ull * 2048ull];
__device__ __nv_bfloat16 g_S1h[2048ull * 2048ull];
__device__ float g_inv_row[NN];
__device__ float g_inv_col[NN];
__device__ float g_colpart[16][NN];
__device__ __nv_bfloat16 g_Xh[10ull * 2048ull * 4096ull]; // bf16 term mirrors
__device__ float g_U[2048ull * 32ull * 64ull];            // u gate, [n][b][o]
__device__ __nv_bfloat16 g_Wr[199680];                    // 4 reordered weight sets

#define WR_G0 0
#define WR_C0 51200
#define WR_G1 76800
#define WR_C1 158720

// ----------------------------- PTX helpers ----------------------------------

__device__ __forceinline__ uint32_t smem_u32(const void* p) {
    uint32_t r;
    asm("{ .reg .u64 t; cvta.to.shared.u64 t, %1; cvt.u32.u64 %0, t; }" : "=r"(r) : "l"(p));
    return r;
}

__device__ __forceinline__ void cp16(uint32_t sm, const void* g, int srcsize) {
    asm volatile("cp.async.cg.shared.global [%0], [%1], 16, %2;"
                 :: "r"(sm), "l"(g), "r"(srcsize) : "memory");
}
#define CP_COMMIT() asm volatile("cp.async.commit_group;" ::: "memory")
#define CP_WAIT2()  asm volatile("cp.async.wait_group 2;" ::: "memory")

__device__ __forceinline__ void ldmA(uint32_t* r, uint32_t addr) {
    asm volatile("ldmatrix.sync.aligned.m8n8.x4.shared.b16 {%0,%1,%2,%3}, [%4];"
                 : "=r"(r[0]), "=r"(r[1]), "=r"(r[2]), "=r"(r[3]) : "r"(addr));
}

__device__ __forceinline__ void ldm4t(uint32_t* r, uint32_t addr) {
    asm volatile("ldmatrix.sync.aligned.m8n8.x4.trans.shared.b16 {%0,%1,%2,%3}, [%4];"
                 : "=r"(r[0]), "=r"(r[1]), "=r"(r[2]), "=r"(r[3]) : "r"(addr));
}

__device__ __forceinline__ void mma16816(float* c, const uint32_t* a, const uint32_t* b) {
    asm volatile(
        "mma.sync.aligned.m16n8k16.row.col.f32.bf16.bf16.f32 "
        "{%0,%1,%2,%3},{%4,%5,%6,%7},{%8,%9},{%0,%1,%2,%3};"
        : "+f"(c[0]), "+f"(c[1]), "+f"(c[2]), "+f"(c[3])
        : "r"(a[0]), "r"(a[1]), "r"(a[2]), "r"(a[3]), "r"(b[0]), "r"(b[1]));
}

// ------------------------------ support prep --------------------------------

__global__ void rowsum_kernel(const float* __restrict__ adj) {
    int row = blockIdx.x, tid = threadIdx.x;
    float s = 0.f;
    for (int k = tid; k < NN; k += 256) s += adj[(size_t)row * NN + k];
    __shared__ float sm[256];
    sm[tid] = s; __syncthreads();
    for (int o = 128; o > 0; o >>= 1) { if (tid < o) sm[tid] += sm[tid + o]; __syncthreads(); }
    if (tid == 0) g_inv_row[row] = 1.0f / fmaxf(sm[0], 1e-8f);
}

// column sums, two-stage: 64x16 partial blocks then tiny reduce (widened from
// a 64-CTA single-stage sweep)
__global__ void colsum_part(const float* __restrict__ adj) {
    int j = blockIdx.x * 32 + threadIdx.x;
    int seg = blockIdx.y, ty = threadIdx.y;
    float s = 0.f;
    for (int k = seg * 128 + ty; k < (seg + 1) * 128; k += 8)
        s += adj[(size_t)k * NN + j];
    __shared__ float sm[8][32];
    sm[ty][threadIdx.x] = s; __syncthreads();
    if (ty == 0) {
        float t = 0.f;
        #pragma unroll
        for (int r = 0; r < 8; r++) t += sm[r][threadIdx.x];
        g_colpart[seg][j] = t;
    }
}

__global__ void colsum_fin() {
    int j = blockIdx.x * 256 + threadIdx.x;
    float t = 0.f;
    #pragma unroll
    for (int s = 0; s < 16; s++) t += g_colpart[s][j];
    g_inv_col[j] = 1.0f / fmaxf(t, 1e-8f);
}

__global__ void build_supports(const float* __restrict__ adj) {
    __shared__ float t[32][33];
    int tx = threadIdx.x, ty = threadIdx.y;
    int j0 = blockIdx.x * 32, i0 = blockIdx.y * 32;
    #pragma unroll
    for (int s = 0; s < 4; s++) {
        int r = ty + s * 8;
        t[r][tx] = adj[(size_t)(i0 + r) * NN + j0 + tx];
    }
    __syncthreads();
    float icol = g_inv_col[j0 + tx];
    float irow = g_inv_row[i0 + tx];
    #pragma unroll
    for (int s = 0; s < 4; s++) {
        int r = ty + s * 8;
        g_S1h[(size_t)(i0 + r) * NN + j0 + tx] = __float2bfloat16(t[r][tx] * icol);
        g_S0h[(size_t)(j0 + r) * NN + i0 + tx] = __float2bfloat16(t[tx][r] * irow);
    }
}

// ----------------- x0 packing (both layers, one launch) ----------------------

__global__ void pack_kernel(const float* __restrict__ inp,
                            const float* __restrict__ hx0,
                            const float* __restrict__ hx1)
{
    __shared__ float sm[65 * 33];
    int n = blockIdx.x, tid = threadIdx.x;
    if (blockIdx.y == 0) {
        // L0 mirror 0: [inp | hx0], stride 2112
        for (int idx = tid; idx < 2048; idx += 256) {
            int b = idx >> 6, u = idx & 63;
            sm[(u + 1) * 33 + b] = hx0[(size_t)b * (NN * UU) + (size_t)n * UU + u];
        }
        if (tid < 32) sm[tid] = inp[(size_t)tid * NN + n];
        __syncthreads();
        for (int idx = tid; idx < 65 * 32; idx += 256) {
            int f = idx >> 5, b = idx & 31;
            g_Xh[(size_t)n * 2112 + idx] = __float2bfloat16(sm[f * 33 + b]);
        }
    } else {
        // L1 mirror 5 hx1-half (cols 2048..4095); h0-half by L0 cand epilogue
        for (int idx = tid; idx < 2048; idx += 256) {
            int b = idx >> 6, u = idx & 63;
            sm[u * 33 + b] = hx1[(size_t)b * (NN * UU) + (size_t)n * UU + u];
        }
        __syncthreads();
        for (int idx = tid; idx < 64 * 32; idx += 256) {
            int f = idx >> 5, b = idx & 31;
            g_Xh[5 * MIRSZ + (size_t)n * 4096 + (size_t)(64 + f) * 32 + b] =
                __float2bfloat16(sm[f * 33 + b]);
        }
    }
}

// ------------------- diffusion GEMM (mma.sync bf16) -------------------------
// Yh = bf16(alpha*(S @ Xh[:,cols]) + beta*Xp[:,cols]); Xp is a bf16 mirror.
// CTA 128x128, k-chunk 32, 4-stage cp.async; 256 threads = 8 warps; occ 2.

#define D_AST 40
#define D_BST 136
#define D_ASB (128 * D_AST * 2)
#define D_BSB (32 * D_BST * 2)
#define DIFF_SMEM (4 * (D_ASB + D_BSB))   // 75776 bytes

__device__ __forceinline__ void diff_body(
    const __nv_bfloat16* __restrict__ S, const __nv_bfloat16* __restrict__ Xh,
    const __nv_bfloat16* __restrict__ Xp, __nv_bfloat16* __restrict__ Yh,
    int ldh, int colOff, int colEnd,
    float alpha, float beta, uint32_t aBase, uint32_t bBase)
{
    const int tid  = threadIdx.x;
    const int row0 = blockIdx.y * 128;
    const int col0 = colOff + blockIdx.x * 128;

    const int wid = tid >> 5, lane = tid & 31;
    const int wm = (wid & 1) * 64;
    const int wn = (wid >> 1) * 32;

    const int aR = (lane & 7) + ((lane >> 3) & 1) * 8;
    const int aC = (lane >> 4) * 8;
    const int bR = ((lane >> 3) & 1) * 8 + (lane & 7);
    const int bC = (lane >> 4) * 8;

    float acc[4][4][4];
    #pragma unroll
    for (int mi = 0; mi < 4; mi++)
        #pragma unroll
        for (int ni = 0; ni < 4; ni++)
            #pragma unroll
            for (int q = 0; q < 4; q++) acc[mi][ni][q] = 0.f;

    auto LOAD = [&](int i) {
        const int k0 = i * 32, s = i & 3;
        #pragma unroll
        for (int t = 0; t < 2; t++) {           // 512 uint4 for A (128 rows x 4)
            int aIdx = t * 256 + tid;
            int r = aIdx >> 2, kq = aIdx & 3;
            cp16(aBase + s * D_ASB + (uint32_t)(r * D_AST + kq * 8) * 2,
                 S + (size_t)(row0 + r) * NN + k0 + kq * 8, 16);
        }
        #pragma unroll
        for (int t = 0; t < 2; t++) {           // 512 uint4 for B (32 rows x 16)
            int bIdx = t * 256 + tid;
            int kr = bIdx >> 4, nq = bIdx & 15;
            int c = col0 + nq * 8;
            cp16(bBase + s * D_BSB + (uint32_t)(kr * D_BST + nq * 8) * 2,
                 Xh + (size_t)(k0 + kr) * ldh + c, (c < colEnd) ? 16 : 0);
        }
    };

    LOAD(0); CP_COMMIT();
    LOAD(1); CP_COMMIT();
    LOAD(2); CP_COMMIT();

    for (int i = 0; i < 64; i++) {
        CP_WAIT2();
        __syncthreads();                // iter i-1 reads done before stage overwrite
        if (i + 3 < 64) LOAD(i + 3);
        CP_COMMIT();

        const int s = i & 3;
        #pragma unroll
        for (int kc = 0; kc < 32; kc += 16) {
            uint32_t af[4][4], bf[2][4];
            #pragma unroll
            for (int mi = 0; mi < 4; mi++)
                ldmA(af[mi], aBase + s * D_ASB +
                     (uint32_t)((wm + mi * 16 + aR) * D_AST + kc + aC) * 2);
            #pragma unroll
            for (int np = 0; np < 2; np++)
                ldm4t(bf[np], bBase + s * D_BSB +
                      (uint32_t)((kc + bR) * D_BST + wn + np * 16 + bC) * 2);
            #pragma unroll
            for (int mi = 0; mi < 4; mi++)
                #pragma unroll
                for (int ni = 0; ni < 4; ni++)
                    mma16816(acc[mi][ni], af[mi], &bf[ni >> 1][(ni & 1) * 2]);
        }
    }

    const int g = lane >> 2, t2 = (lane & 3) * 2;
    #pragma unroll
    for (int mi = 0; mi < 4; mi++) {
        #pragma unroll
        for (int half = 0; half < 2; half++) {
            int r = row0 + wm + mi * 16 + g + half * 8;
            const __nv_bfloat16* pRow = Xp ? (Xp + (size_t)r * ldh) : nullptr;
            __nv_bfloat16* hRow = Yh + (size_t)r * ldh;
            #pragma unroll
            for (int ni = 0; ni < 4; ni++) {
                int c = col0 + wn + ni * 8 + t2;
                if (c < colEnd) {
                    float vx = alpha * acc[mi][ni][half * 2 + 0];
                    float vy = alpha * acc[mi][ni][half * 2 + 1];
                    if (pRow) {
                        __nv_bfloat162 p = *(const __nv_bfloat162*)(pRow + c);
                        vx = fmaf(beta, __bfloat162float(p.x), vx);
                        vy = fmaf(beta, __bfloat162float(p.y), vy);
                    }
                    *(__nv_bfloat162*)(hRow + c) = __floats2bfloat162_rn(vx, vy);
                }
            }
        }
    }
}

// indices are mirror-buffer numbers; symbol arithmetic stays in-kernel.
__global__ void __launch_bounds__(256, 2)
diff_mma(int sSel, int xhIdx, int prevIdx, int yhIdx,
         int ldh, int colOff, int colEnd, float alpha, float beta)
{
    extern __shared__ __nv_bfloat16 dsm[];
    const uint32_t aBase = smem_u32(dsm);
    diff_body(sSel ? g_S1h : g_S0h,
              g_Xh + (size_t)xhIdx * MIRSZ,
              (prevIdx >= 0) ? (g_Xh + (size_t)prevIdx * MIRSZ) : nullptr,
              g_Xh + (size_t)yhIdx * MIRSZ,
              ldh, colOff, colEnd, alpha, beta, aBase, aBase + 4 * D_ASB);
}

// buf2 and buf3 both depend only on buf1 -> one launch; layer selects buffers.
__global__ void __launch_bounds__(256, 2)
diff_pair(int layer, int ldh, int colOff, int colEnd)
{
    extern __shared__ __nv_bfloat16 dsm[];
    const uint32_t aBase = smem_u32(dsm);
    const int mb = layer * 5;
    if (blockIdx.z == 0) {
        // buf2 = 2*S0@buf1 - buf0
        diff_body(g_S0h, g_Xh + (size_t)(mb + 1) * MIRSZ,
                  g_Xh + (size_t)(mb + 0) * MIRSZ, g_Xh + (size_t)(mb + 2) * MIRSZ,
                  ldh, colOff, colEnd, 2.0f, -1.0f, aBase, aBase + 4 * D_ASB);
    } else {
        // buf3 = S1@buf1
        diff_body(g_S1h, g_Xh + (size_t)(mb + 1) * MIRSZ,
                  nullptr, g_Xh + (size_t)(mb + 3) * MIRSZ,
                  ldh, colOff, colEnd, 1.0f, 0.0f, aBase, aBase + 4 * D_ASB);
    }
}

// --------------- weight reorder (all four sets, one launch) ------------------

__device__ __forceinline__ void wprep_one(const float* __restrict__ W,
                                          __nv_bfloat16* __restrict__ dst,
                                          int F, int Fp, int O) {
    int idx = blockIdx.x * 256 + threadIdx.x;
    if (idx >= 5 * Fp * O) return;
    int o = idx % O;
    int rest = idx / O;
    int f = rest % Fp;
    int m = rest / Fp;
    dst[idx] = (f < F) ? __float2bfloat16(W[(size_t)(f * 5 + m) * O + o])
                       : __float2bfloat16(0.f);
}

__global__ void wprep_all(const float* wg0, const float* wc0,
                          const float* wg1, const float* wc1) {
    switch (blockIdx.y) {
        case 0: wprep_one(wg0, g_Wr + WR_G0, 65, 80, 128); break;
        case 1: wprep_one(wc0, g_Wr + WR_C0, 65, 80, 64); break;
        case 2: wprep_one(wg1, g_Wr + WR_G1, 128, 128, 128); break;
        case 3: wprep_one(wc1, g_Wr + WR_C1, 128, 128, 64); break;
    }
}

// ------------------------ W-GEMM (mma.sync bf16) ----------------------------
// xhBase: first mirror index of this layer (0 or 5); wrOff: offset into g_Wr.
// MODE 0 (gate): sigmoid; o<64 -> r*hx into this layer's mirror buf0 at FinB;
//                o>=64 -> g_U.
// MODE 1 (cand): tanh; h -> hout; packFlag also writes h into L1 mirror 5.

#define W_ST 136

template <int O, int MODE>
__global__ void __launch_bounds__(256)
wgemm_mma(int F, int Fp, int ldh, int xhBase, int wrOff,
          const float* __restrict__ bias,
          const float* __restrict__ hx, float* __restrict__ hout,
          int FinB, int gMirBuf, int packFlag)
{
    constexpr int NI = O / 32;
    __shared__ __nv_bfloat16 As[4][16 * W_ST];
    __shared__ __nv_bfloat16 Ws[4][16 * W_ST];

    const __nv_bfloat16* __restrict__ XhL = g_Xh + (size_t)xhBase * MIRSZ;
    const __nv_bfloat16* __restrict__ Wr  = g_Wr + wrOff;

    const int tid = threadIdx.x;
    const int n0  = blockIdx.x * 4;
    const int wid = tid >> 5, lane = tid & 31;
    const int wm  = (wid & 1) * 64;
    const int wn  = (wid >> 1) * (O / 4);

    const int chunksPerM = Fp / 16;
    const int total = 5 * chunksPerM;

    const int kfA = tid >> 4, lnA = (tid >> 2) & 3, qA = tid & 3;
    const int kfW = tid >> 4, qW = tid & 15;

    const int ktA = (lane & 7) + ((lane >> 4) & 1) * 8;
    const int mcA = ((lane >> 3) & 1) * 8;
    const int bR = ((lane >> 3) & 1) * 8 + (lane & 7);
    const int bC = (lane >> 4) * 8;

    const uint32_t asB = smem_u32(As), wsB = smem_u32(Ws);

    float acc[4][NI][4];
    #pragma unroll
    for (int mt = 0; mt < 4; mt++)
        #pragma unroll
        for (int ni = 0; ni < NI; ni++)
            #pragma unroll
            for (int q = 0; q < 4; q++) acc[mt][ni][q] = 0.f;

    auto LOAD = [&](int ic) {
        const int s = ic & 3;
        const int mi = ic / chunksPerM;
        const int fc = (ic % chunksPerM) * 16;
        const int f = fc + kfA;
        cp16(asB + (uint32_t)(s * 16 * W_ST + kfA * W_ST + lnA * 32 + qA * 8) * 2,
             XhL + (size_t)mi * MIRSZ + (size_t)(n0 + lnA) * ldh + (size_t)f * 32 + qA * 8,
             (f < F) ? 16 : 0);
        if (qW * 8 < O)
            cp16(wsB + (uint32_t)(s * 16 * W_ST + kfW * W_ST + qW * 8) * 2,
                 Wr + ((size_t)mi * Fp + fc + kfW) * O + qW * 8, 16);
    };

    LOAD(0); CP_COMMIT();
    LOAD(1); CP_COMMIT();
    LOAD(2); CP_COMMIT();

    for (int ic = 0; ic < total; ic++) {
        CP_WAIT2();
        __syncthreads();
        if (ic + 3 < total) LOAD(ic + 3);
        CP_COMMIT();

        const int s = ic & 3;
        uint32_t af[4][4];
        #pragma unroll
        for (int mt = 0; mt < 4; mt++)
            ldm4t(af[mt], asB +
                  (uint32_t)(s * 16 * W_ST + ktA * W_ST + wm + mt * 16 + mcA) * 2);
        uint32_t bf[(NI + 1) / 2][4];
        #pragma unroll
        for (int np = 0; np < (NI + 1) / 2; np++)
            ldm4t(bf[np], wsB +
                  (uint32_t)(s * 16 * W_ST + bR * W_ST + wn + np * 16 + bC) * 2);
        #pragma unroll
        for (int mt = 0; mt < 4; mt++)
            #pragma unroll
            for (int ni = 0; ni < NI; ni++)
                mma16816(acc[mt][ni], af[mt], &bf[ni >> 1][(ni & 1) * 2]);
    }

    const int g = lane >> 2, t2 = (lane & 3) * 2;
    #pragma unroll
    for (int mt = 0; mt < 4; mt++) {
        #pragma unroll
        for (int half = 0; half < 2; half++) {
            int r = wm + mt * 16 + g + half * 8;
            int ln = r >> 5, b = r & 31, n = n0 + ln;
            #pragma unroll
            for (int ni = 0; ni < NI; ni++) {
                int o = wn + ni * 8 + t2;
                float p0 = acc[mt][ni][half * 2 + 0] + bias[o];
                float p1 = acc[mt][ni][half * 2 + 1] + bias[o + 1];
                if (MODE == 0) {
                    float v0 = 1.0f / (1.0f + __expf(-p0));
                    float v1 = 1.0f / (1.0f + __expf(-p1));
                    if (o < 64) {
                        float hp0 = hx[(size_t)b * (NN * UU) + (size_t)n * UU + o];
                        float hp1 = hx[(size_t)b * (NN * UU) + (size_t)n * UU + o + 1];
                        __nv_bfloat16* dH = g_Xh + (size_t)gMirBuf * MIRSZ +
                                            (size_t)n * ldh + FinB;
                        dH[(size_t)o * 32 + b] = __float2bfloat16(v0 * hp0);
                        dH[(size_t)(o + 1) * 32 + b] = __float2bfloat16(v1 * hp1);
                    } else {
                        *(float2*)&g_U[((size_t)n * 32 + b) * 64 + (o - 64)] = make_float2(v0, v1);
                    }
                } else {
                    float c0 = tanhf(p0), c1 = tanhf(p1);
                    float2 uv = *(const float2*)&g_U[((size_t)n * 32 + b) * 64 + o];
                    float hp0 = hx[(size_t)b * (NN * UU) + (size_t)n * UU + o];
                    float hp1 = hx[(size_t)b * (NN * UU) + (size_t)n * UU + o + 1];
                    float h0v = uv.x * hp0 + (1.0f - uv.x) * c0;
                    float h1v = uv.y * hp1 + (1.0f - uv.y) * c1;
                    *(float2*)&hout[(size_t)b * (NN * UU) + (size_t)n * UU + o] = make_float2(h0v, h1v);
                    if (packFlag) {  // h0 straight into L1 mirror 5, cols o*32+b
                        __nv_bfloat16* pH = g_Xh + 5 * MIRSZ + (size_t)n * 4096;
                        pH[(size_t)o * 32 + b] = __float2bfloat16(h0v);
                        pH[(size_t)(o + 1) * 32 + b] = __float2bfloat16(h1v);
                    }
                }
            }
        }
    }
}

// ------------------------------ projection ----------------------------------

__global__ void proj_kernel(const float* __restrict__ h1, const float* __restrict__ wp,
                            const float* __restrict__ bp, float* __restrict__ out)
{
    int warp = (blockIdx.x * blockDim.x + threadIdx.x) >> 5;
    int lane = threadIdx.x & 31;
    if (warp >= BB * NN) return;
    int b = warp >> 11, n = warp & (NN - 1);
    const float* hr = h1 + (size_t)b * (NN * UU) + (size_t)n * UU;
    float s = hr[lane] * wp[lane] + hr[lane + 32] * wp[lane + 32];
    #pragma unroll
    for (int o = 16; o > 0; o >>= 1) s += __shfl_down_sync(0xffffffffu, s, o);
    if (lane == 0) out[(size_t)b * NN + n] = s + bp[0];
}

// ------------------------------ driver --------------------------------------

static void run_diffusion(int layer, int colOff, int colW, int ldh) {
    int tiles = (colW + 127) / 128;
    int ce = colOff + colW;
    int mb = layer * 5;
    diff_mma <<<dim3(tiles, 16),    256, DIFF_SMEM>>>(0, mb + 0, -1, mb + 1,
                                                      ldh, colOff, ce, 1.0f, 0.0f);
    diff_pair<<<dim3(tiles, 16, 2), 256, DIFF_SMEM>>>(layer, ldh, colOff, ce);
    diff_mma <<<dim3(tiles, 16),    256, DIFF_SMEM>>>(1, mb + 3, mb + 1, mb + 4,
                                                      ldh, colOff, ce, 2.0f, -1.0f);
}

extern "C" void kernel_launch(void* const* d_in, const int* in_sizes, int n_in,
                              void* d_out, int out_size)
{
    const float* inputs = (const float*)d_in[0];
    const float* hidden = (const float*)d_in[1];
    const float* adj    = (const float*)d_in[2];
    const float* wg0    = (const float*)d_in[3];
    const float* bg0    = (const float*)d_in[4];
    const float* wc0    = (const float*)d_in[5];
    const float* bc0    = (const float*)d_in[6];
    const float* wg1    = (const float*)d_in[7];
    const float* bg1    = (const float*)d_in[8];
    const float* wc1    = (const float*)d_in[9];
    const float* bc1    = (const float*)d_in[10];
    const float* wproj  = (const float*)d_in[11];
    const float* bproj  = (const float*)d_in[12];

    float* out = (float*)d_out;                       // (B, N)
    float* h0  = out + (size_t)BB * NN;               // (B, N*U)
    float* h1  = h0 + (size_t)BB * NN * UU;           // (B, N*U)
    const float* hx0 = hidden;
    const float* hx1 = hidden + (size_t)BB * NN * UU;

    cudaFuncSetAttribute(diff_mma,  cudaFuncAttributeMaxDynamicSharedMemorySize, DIFF_SMEM);
    cudaFuncSetAttribute(diff_pair, cudaFuncAttributeMaxDynamicSharedMemorySize, DIFF_SMEM);

    // startup: supports + input packing + all weight reorders
    rowsum_kernel<<<NN, 256>>>(adj);
    colsum_part<<<dim3(NN / 32, 16), dim3(32, 8)>>>(adj);
    colsum_fin<<<NN / 256, 256>>>();
    build_supports<<<dim3(NN / 32, NN / 32), dim3(32, 8)>>>(adj);
    pack_kernel<<<dim3(NN, 2), 256>>>(inputs, hx0, hx1);
    wprep_all<<<dim3(320, 4), 256>>>(wg0, wc0, wg1, wc1);

    // ---- layer 0 (F = 65 -> Fp = 80; mirrors 0..4, stride 2112) ----
    run_diffusion(0, 0, 2080, 2112);
    wgemm_mma<128, 0><<<NN / 4, 256>>>(65, 80, 2112, 0, WR_G0, bg0, hx0,
                                       nullptr, 32, 0, 0);
    run_diffusion(0, 32, 2048, 2112);
    wgemm_mma<64, 1><<<NN / 4, 256>>>(65, 80, 2112, 0, WR_C0, bc0, hx0,
                                      h0, 0, 0, 1);

    // ---- layer 1 (F = 128 = Fp; mirrors 5..9, stride 4096) ----
    run_diffusion(1, 0, 4096, 4096);
    wgemm_mma<128, 0><<<NN / 4, 256>>>(128, 128, 4096, 5, WR_G1, bg1, hx1,
                                       nullptr, 2048, 5, 0);
    run_diffusion(1, 2048, 2048, 4096);
    wgemm_mma<64, 1><<<NN / 4, 256>>>(128, 128, 4096, 5, WR_C1, bc1, hx1,
                                      h1, 0, 0, 0);

    // projection
    proj_kernel<<<(BB * NN) / 8, 256>>>(h1, wproj, bproj, out);
}